// round 14
// baseline (speedup 1.0000x reference)
#include <cuda_runtime.h>
#include <cuda_fp16.h>
#include <cuda_bf16.h>

// Problem constants (from reference_code)
#define N_PATHS  10000000
#define MAX_LEN  3
#define N_NODES  100000
#define HIDDEN   128

#define GATHER_BLOCKS  1184   // 148 SMs x 8 CTAs (256 thr, <=32 regs)
#define GATHER_THREADS 256

// fp16 planar projection table: g_t16[l * N_NODES + node], 600 KB total.
__device__ __half g_t16[3 * N_NODES];

// ---------------------------------------------------------------------------
// Kernel 1: proj[l][node] = dot(feature[node], W[l][0]) -> fp16 planar table.
// R12 body (4 lanes/node, 8 nodes/warp, 2-level shuffle reduce). DRAM-bound.
// ---------------------------------------------------------------------------
__global__ void __launch_bounds__(256)
proj_kernel(const float* __restrict__ nf, const float* __restrict__ W) {
    const int lane   = threadIdx.x & 31;
    const int sub    = lane & 3;
    const int nin    = lane >> 2;
    const int warpId = (blockIdx.x * blockDim.x + threadIdx.x) >> 5;
    const int node   = warpId * 8 + nin;
    if (node >= N_NODES) return;

    const float4* nf4 = ((const float4*)nf) + (size_t)node * 32 + sub;
    const float4* w4  = (const float4*)W;

    float s0 = 0.0f, s1 = 0.0f, s2 = 0.0f;
    #pragma unroll
    for (int k = 0; k < 8; k++) {
        const float4 f = __ldcs(nf4 + 4 * k);
        const float4 a = __ldg(w4 + 0  + sub + 4 * k);
        const float4 b = __ldg(w4 + 32 + sub + 4 * k);
        const float4 c = __ldg(w4 + 64 + sub + 4 * k);
        s0 += f.x * a.x + f.y * a.y + f.z * a.z + f.w * a.w;
        s1 += f.x * b.x + f.y * b.y + f.z * b.z + f.w * b.w;
        s2 += f.x * c.x + f.y * c.y + f.z * c.z + f.w * c.w;
    }

    s0 += __shfl_xor_sync(0xFFFFFFFFu, s0, 1);
    s1 += __shfl_xor_sync(0xFFFFFFFFu, s1, 1);
    s2 += __shfl_xor_sync(0xFFFFFFFFu, s2, 1);
    s0 += __shfl_xor_sync(0xFFFFFFFFu, s0, 2);
    s1 += __shfl_xor_sync(0xFFFFFFFFu, s1, 2);
    s2 += __shfl_xor_sync(0xFFFFFFFFu, s2, 2);

    if (sub == 0) {
        g_t16[0 * N_NODES + node] = __float2half(s0);
        g_t16[1 * N_NODES + node] = __float2half(s1);
        g_t16[2 * N_NODES + node] = __float2half(s2);
    }
}

// Protected R7 gather body for one quad of paths.
__device__ __forceinline__ void process_quad(const int idx[12], float4* res) {
    float* r = (float*)res;
    #pragma unroll
    for (int k = 0; k < 4; k++) {
        float s = 0.0f;
        int   cnt = 0;
        #pragma unroll
        for (int l = 0; l < 3; l++) {
            const int p = idx[k * 3 + l];
            if (p >= 0) {                     // predicated LDG + SEL (no branch)
                s += __half2float(g_t16[l * N_NODES + p]);
                cnt++;
            }
        }
        float inv = (cnt == 3) ? (1.0f / 3.0f)
                               : ((cnt == 2) ? 0.5f : 1.0f);
        r[k] = s * inv;
    }
}

// ---------------------------------------------------------------------------
// Kernel 2: persistent single-wave gather with PDL.
// Every thread pre-loads its FIRST iteration's paths before the dependency
// sync, so that traffic (14.5 MB) plus the whole-grid ramp overlaps proj.
// Remaining ~7 iterations run grid-strided (no further wave ramps).
// Inner gather loop identical to the floor-proven R7 code.
// ---------------------------------------------------------------------------
__global__ void __launch_bounds__(GATHER_THREADS)
gather_kernel(const int* __restrict__ paths, float* __restrict__ out) {
    const long long QT     = N_PATHS / 4;                       // 2.5M quads
    const long long stride = (long long)GATHER_BLOCKS * GATHER_THREADS;
    const long long q0     = (long long)blockIdx.x * blockDim.x + threadIdx.x;

    // Pre-dependency: stream in iteration-0 paths (independent of proj)
    int4 v0, v1, v2;
    if (q0 < QT) {
        const int4* p4 = ((const int4*)paths) + q0 * 3;
        v0 = __ldcs(p4 + 0);
        v1 = __ldcs(p4 + 1);
        v2 = __ldcs(p4 + 2);
    }

    cudaGridDependencySynchronize();   // proj table complete + visible

    if (q0 < QT) {
        const int idx[12] = { v0.x, v0.y, v0.z, v0.w,
                              v1.x, v1.y, v1.z, v1.w,
                              v2.x, v2.y, v2.z, v2.w };
        float4 res;
        process_quad(idx, &res);
        __stcs(((float4*)out) + q0, res);
    }

    for (long long q = q0 + stride; q < QT; q += stride) {
        const int4* p4 = ((const int4*)paths) + q * 3;
        int4 a0 = __ldcs(p4 + 0);
        int4 a1 = __ldcs(p4 + 1);
        int4 a2 = __ldcs(p4 + 2);
        const int idx[12] = { a0.x, a0.y, a0.z, a0.w,
                              a1.x, a1.y, a1.z, a1.w,
                              a2.x, a2.y, a2.z, a2.w };
        float4 res;
        process_quad(idx, &res);
        __stcs(((float4*)out) + q, res);
    }
}

// ---------------------------------------------------------------------------
// Launch. Inputs identified by element count:
//   30,000,000 -> paths (int32 [10M,3]); 12,800,000 -> node_feature; 384 -> W
// ---------------------------------------------------------------------------
extern "C" void kernel_launch(void* const* d_in, const int* in_sizes, int n_in,
                              void* d_out, int out_size) {
    const void*  paths_raw = nullptr;
    const float* nf        = nullptr;
    const float* W         = nullptr;

    for (int i = 0; i < n_in; i++) {
        if      (in_sizes[i] == N_PATHS * MAX_LEN)  paths_raw = d_in[i];
        else if (in_sizes[i] == N_NODES * HIDDEN)   nf        = (const float*)d_in[i];
        else if (in_sizes[i] == MAX_LEN * HIDDEN)   W         = (const float*)d_in[i];
    }

    float* out = (float*)d_out;

    // proj: 8 nodes per warp -> 12500 warps -> 1563 blocks of 256
    {
        const int threads = 256;
        const int warps   = (N_NODES + 7) / 8;
        const int blocks  = (warps * 32 + threads - 1) / threads;
        proj_kernel<<<blocks, threads>>>(nf, W);
    }

    // persistent gather with PDL overlap
    {
        cudaLaunchAttribute attrs[1];
        attrs[0].id = cudaLaunchAttributeProgrammaticStreamSerialization;
        attrs[0].val.programmaticStreamSerializationAllowed = 1;

        cudaLaunchConfig_t cfg = {};
        cfg.gridDim  = dim3(GATHER_BLOCKS, 1, 1);
        cfg.blockDim = dim3(GATHER_THREADS, 1, 1);
        cfg.dynamicSmemBytes = 0;
        cfg.stream   = 0;
        cfg.attrs    = attrs;
        cfg.numAttrs = 1;

        cudaLaunchKernelEx(&cfg, gather_kernel,
                           (const int*)paths_raw, out);
    }
}